// round 16
// baseline (speedup 1.0000x reference)
#include <cuda_runtime.h>
#include <cstdint>

#define N_  2
#define C_  64
#define H_  256
#define W_  256
#define HW  (H_*W_)
#define HD  128
#define WD  128
#define HWD (HD*WD)
#define KK  25
#define KP  28                      // padded k-vector stride (112B, float4-aligned)
#define CGS28 (N_*HWD*KP)           // per-channel-group partial stride (padded)
#define OSTR (N_*64*HWD)            // per-half partial-out stride = 2,097,152

// scratch (device globals per allocation-free rule)
__device__ __align__(16) float2 g_w2d[C_*KK*9];      // folded enc weights, dup'd, [ci][kk][t]
__device__ __align__(16) float g_tb[KK*9];           // per-tap folded bias
__device__ __align__(16) float2 g_owp[C_*4*32];      // out weights packed [c][q][j]={ow[j][4c+q],ow[j+32][4c+q]}
__device__ __align__(16) float g_part[4*CGS28];      // partial logits (padded), 14.7 MB
__device__ __align__(16) float g_k[N_*HWD*KP];       // softmax weights (n,hd,wd,28)
__device__ __align__(16) float g_pout[2*OSTR];       // per-half partial outputs, 16.8MB ea

// cp.async helpers
__device__ __forceinline__ void cp_async4(uint32_t dst_smem, const void* src, bool valid) {
    int sz = valid ? 4 : 0;
    asm volatile("cp.async.ca.shared.global [%0], [%1], 4, %2;\n"
                 :: "r"(dst_smem), "l"(src), "r"(sz));
}
__device__ __forceinline__ void cp_async8(uint32_t dst_smem, const void* src) {
    asm volatile("cp.async.ca.shared.global [%0], [%1], 8;\n"
                 :: "r"(dst_smem), "l"(src));
}
__device__ __forceinline__ void cp_async16z(uint32_t dst_smem, const void* src, bool valid) {
    int sz = valid ? 16 : 0;
    asm volatile("cp.async.ca.shared.global [%0], [%1], 16, %2;\n"
                 :: "r"(dst_smem), "l"(src), "r"(sz));
}
__device__ __forceinline__ void cp_async_commit() {
    asm volatile("cp.async.commit_group;\n");
}

// ---- packed fp32x2 helpers (sm_103a FFMA2) ----
__device__ __forceinline__ unsigned long long pack2(float lo, float hi) {
    unsigned long long r;
    asm("mov.b64 %0, {%1, %2};" : "=l"(r) : "f"(lo), "f"(hi));
    return r;
}
__device__ __forceinline__ void fma2(unsigned long long& d,
                                     unsigned long long a, unsigned long long b) {
    asm("fma.rn.f32x2 %0, %1, %2, %0;" : "+l"(d) : "l"(a), "l"(b));
}
__device__ __forceinline__ float2 unpack2(unsigned long long v) {
    float lo, hi;
    asm("mov.b64 {%0, %1}, %2;" : "=f"(lo), "=f"(hi) : "l"(v));
    return make_float2(lo, hi);
}

// ---------------------------------------------------------------------------
// Kernel 0: fold down(1x1) into enc(3x3). Also per-tap bias.
// ---------------------------------------------------------------------------
__global__ void k_w2(const float* __restrict__ ew,
                     const float* __restrict__ dw,
                     const float* __restrict__ db) {
    __shared__ float sew[576];
    __shared__ float sdb[64];
    __shared__ float sdw[64*64];
    const int kk = blockIdx.x;
    const int t  = threadIdx.x;
    sew[t] = ew[kk*576 + t];
    if (t < 64) sdb[t] = db[t];
    for (int i = t; i < 4096; i += 576) sdw[i] = dw[i];
    __syncthreads();

    const int ci = t / 9, rs = t % 9;
    float s = 0.f;
#pragma unroll 8
    for (int c = 0; c < 64; c++) s += sew[c*9 + rs] * sdw[c*64 + ci];
    g_w2d[(ci * KK + kk) * 9 + rs] = make_float2(s, s);

    if (t < 9) {
        float s2 = 0.f;
        for (int c = 0; c < 64; c++) s2 += sew[c*9 + t] * sdb[c];
        g_tb[kk*9 + t] = s2;
    }
}

// ---------------------------------------------------------------------------
// Kernel 0b: pack out-conv weights: g_owp[c][q][j] = {ow[j][4c+q], ow[j+32][4c+q]}
// ---------------------------------------------------------------------------
__global__ void k_owp(const float* __restrict__ ow) {
    const int c = blockIdx.x;        // 0..63
    const int t = threadIdx.x;       // 128: q = t>>5, j = t&31
    const int q = t >> 5, j = t & 31;
    g_owp[c * 128 + q * 32 + j] =
        make_float2(ow[j * 256 + c * 4 + q], ow[(j + 32) * 256 + c * 4 + q]);
}

// ---------------------------------------------------------------------------
// Kernel 1: folded 3x3 stride-2 conv x(64ch) -> 25 partial logits. (unchanged)
// ---------------------------------------------------------------------------
#define ENC_TILE_F (33*36)

__global__ void __launch_bounds__(128) k_enc(const float* __restrict__ x) {
    __shared__ float  tile[2][33][36];
    __shared__ float2 wsd[2][25][9];
    const int n   = blockIdx.z >> 2;
    const int cg  = blockIdx.z & 3;
    const int hd0 = blockIdx.y * 16;
    const int wd0 = blockIdx.x * 16;
    const int tid = threadIdx.x;
    const int tx  = tid & 15;
    const int ty  = tid >> 4;
    const int c0  = cg * 16;

    const int h0 = 2 * hd0 - 1;
    const int w0 = 2 * wd0 - 1;
    const float* src = x + (size_t)n * C_ * HW;
    const uint32_t smem_tile = (uint32_t)__cvta_generic_to_shared(&tile[0][0][0]);
    const uint32_t smem_wsd  = (uint32_t)__cvta_generic_to_shared(&wsd[0][0][0]);

    auto stage = [&](int ci, int buf) {
        const float* sc = src + (size_t)(c0 + ci) * HW;
        const uint32_t tbase = smem_tile + (uint32_t)buf * (ENC_TILE_F * 4);
#pragma unroll
        for (int i = 0; i < 9; i++) {
            int idx = tid + i * 128;
            if (idx < 33*33) {
                int r = idx / 33, cc = idx % 33;
                int h = h0 + r, w = w0 + cc;
                bool ok = (h >= 0 && h < H_ && w >= 0 && w < W_);
                cp_async4(tbase + (uint32_t)(r * 36 + cc) * 4, sc + h * W_ + w, ok);
            }
        }
        const float2* wsrc = g_w2d + (size_t)(c0 + ci) * (KK * 9);
        const uint32_t wbase = smem_wsd + (uint32_t)buf * (KK * 9 * 8);
        cp_async8(wbase + (uint32_t)tid * 8, wsrc + tid);
        if (tid + 128 < 225)
            cp_async8(wbase + (uint32_t)(tid + 128) * 8, wsrc + tid + 128);
        cp_async_commit();
    };

    stage(0, 0);
    stage(1, 1);

    unsigned long long acc2[KK];
#pragma unroll
    for (int kk = 0; kk < KK; kk++) acc2[kk] = 0ULL;

    for (int ci = 0; ci < 16; ci++) {
        if (ci == 15) asm volatile("cp.async.wait_group 0;\n");
        else          asm volatile("cp.async.wait_group 1;\n");
        __syncthreads();

        const float (*tb)[36] = tile[ci & 1];
        unsigned long long v01[9];
#pragma unroll
        for (int r = 0; r < 3; r++)
#pragma unroll
            for (int s = 0; s < 3; s++)
                v01[r*3+s] = pack2(tb[4*ty + r][2*tx + s],
                                   tb[4*ty + 2 + r][2*tx + s]);

        const unsigned long long* wc =
            (const unsigned long long*)&wsd[ci & 1][0][0];
#pragma unroll
        for (int kk = 0; kk < KK; kk++)
#pragma unroll
            for (int t = 0; t < 9; t++)
                fma2(acc2[kk], wc[kk*9 + t], v01[t]);

        if (ci < 14) {
            __syncthreads();
            stage(ci + 2, ci & 1);
        }
    }

    const int wd = wd0 + tx;
    float* dst0 = g_part + cg * CGS28 + ((size_t)((n * HD + hd0 + 2*ty) * WD + wd)) * KP;
    float* dst1 = g_part + cg * CGS28 + ((size_t)((n * HD + hd0 + 2*ty + 1) * WD + wd)) * KP;
#pragma unroll
    for (int kk = 0; kk < KK; kk++) {
        float2 r = unpack2(acc2[kk]);
        dst0[kk] = r.x;
        dst1[kk] = r.y;
    }
}

// ---------------------------------------------------------------------------
// Kernel 2: sum 4 partials + bias + softmax. 128 threads x 256 blocks
// (R13 had 128 blocks < 148 SMs -> occ 12%; more blocks hides latency).
// ---------------------------------------------------------------------------
__global__ void __launch_bounds__(128) k_softmax(const float* __restrict__ eb) {
    __shared__ float stb[225];
    __shared__ float seb[25];
    const int tid = threadIdx.x;
    stb[tid] = g_tb[tid];
    if (tid + 128 < 225) stb[tid + 128] = g_tb[tid + 128];
    if (tid < 25)  seb[tid] = eb[tid];
    __syncthreads();

    const int pix = blockIdx.x * 128 + tid;           // 32768 pixels
    const int wd = pix & 127;
    const int hd = (pix >> 7) & 127;

    const float r0 = (hd != 0) ? 1.f : 0.f;
    const float s0 = (wd != 0) ? 1.f : 0.f;
    float m9[9];
    m9[0] = r0 * s0; m9[1] = r0; m9[2] = r0;
    m9[3] = s0;      m9[4] = 1.f; m9[5] = 1.f;
    m9[6] = s0;      m9[7] = 1.f; m9[8] = 1.f;

    const float4* p0 = (const float4*)(g_part + (size_t)pix * KP);
    const float4* p1 = (const float4*)(g_part + CGS28   + (size_t)pix * KP);
    const float4* p2 = (const float4*)(g_part + 2*CGS28 + (size_t)pix * KP);
    const float4* p3 = (const float4*)(g_part + 3*CGS28 + (size_t)pix * KP);
    float a[28];
#pragma unroll
    for (int i = 0; i < 7; i++) {
        float4 v0 = p0[i], v1 = p1[i], v2 = p2[i], v3 = p3[i];
        a[4*i+0] = v0.x + v1.x + v2.x + v3.x;
        a[4*i+1] = v0.y + v1.y + v2.y + v3.y;
        a[4*i+2] = v0.z + v1.z + v2.z + v3.z;
        a[4*i+3] = v0.w + v1.w + v2.w + v3.w;
    }

    float lg[28];
#pragma unroll
    for (int kk = 0; kk < KK; kk++) {
        float v = a[kk] + seb[kk];
#pragma unroll
        for (int t = 0; t < 9; t++) v += m9[t] * stb[kk*9 + t];
        lg[kk] = v;
    }

    float mx = lg[0];
#pragma unroll
    for (int kk = 1; kk < KK; kk++) mx = fmaxf(mx, lg[kk]);
    float sum = 0.f;
#pragma unroll
    for (int kk = 0; kk < KK; kk++) { lg[kk] = expf(lg[kk] - mx); sum += lg[kk]; }
    float inv = 1.f / sum;
#pragma unroll
    for (int kk = 0; kk < KK; kk++) lg[kk] *= inv;
    lg[25] = 0.f; lg[26] = 0.f; lg[27] = 0.f;

    float4* dst = (float4*)(g_k + (size_t)pix * KP);
#pragma unroll
    for (int i = 0; i < 7; i++)
        dst[i] = make_float4(lg[4*i], lg[4*i+1], lg[4*i+2], lg[4*i+3]);
}

// ---------------------------------------------------------------------------
// Kernel 3: FUSED reassembly + 1x1 out-conv, CHANNEL-SPLIT x2.
// Grid (64 b, 2 n, 2 half) = 256 blocks (2/SM, 16 warps/SM for latency
// hiding — R13's single-block version had 128 blocks and stalled at waits).
// Each half accumulates 32 channels into g_pout[half]; k_red sums + bias.
// ---------------------------------------------------------------------------
#define FB_ROW 272
#define FB_Q   (5*FB_ROW)          // 1360 floats
#define FB_BUF (4*FB_Q)            // 5440 floats per buffer
#define FB_SMEM (2*FB_BUF*4)       // 43,520 B dynamic

__global__ void __launch_bounds__(256) k_fuse(const float* __restrict__ x) {
    extern __shared__ float xs[];              // [2][FB_BUF]
    __shared__ float2 ows2[2][4][32];          // per-channel weight slice
    const int b    = blockIdx.x;               // hd pair: hd in {2b, 2b+1}
    const int n    = blockIdx.y;
    const int half = blockIdx.z;               // 0..1 -> channels half*32..+31
    const int tid  = threadIdx.x;              // 256

    const int ph = tid >> 7;                   // 0..1
    const int hd = 2 * b + ph;
    const int wd = tid & 127;

    const uint32_t xs_u32  = (uint32_t)__cvta_generic_to_shared(xs);
    const uint32_t ow_u32  = (uint32_t)__cvta_generic_to_shared(&ows2[0][0][0]);

    // zero-init both band buffers (edge zeros persist; cp.async covers [8,264))
    for (int i = tid; i < 2 * FB_BUF; i += 256) xs[i] = 0.f;

    // softmax weights for this pixel (7 LDG.128)
    float kw[25];
    {
        const float4* kp = (const float4*)(g_k + (size_t)((n * HD + hd) * WD + wd) * KP);
        float t28[28];
#pragma unroll
        for (int i = 0; i < 7; i++) {
            float4 v = kp[i];
            t28[4*i] = v.x; t28[4*i+1] = v.y; t28[4*i+2] = v.z; t28[4*i+3] = v.w;
        }
#pragma unroll
        for (int kk = 0; kk < KK; kk++) kw[kk] = t28[kk];
    }

    // cout accumulators: acc2[j] = {co=j, co=j+32} (no bias; k_red adds it)
    unsigned long long acc2[32];
#pragma unroll
    for (int j = 0; j < 32; j++) acc2[j] = 0ULL;

    const float* xn = x + (size_t)n * C_ * HW;
    const int q_of = tid >> 6;                 // 0..3: one quadrant row per 64 threads
    const int lane = tid & 63;                 // float4 within row
    const int cbase = half * 32;

    __syncthreads();                           // zero-init visible before cp.async

    auto stage = [&](int c, int buf) {
        const float* src = xn + (size_t)c * HW;
        const uint32_t base = xs_u32 + (uint32_t)buf * (FB_BUF * 4);
#pragma unroll
        for (int r = 0; r < 5; r++) {
            const int h = q_of * 64 + b - 2 + r;
            const bool hv = (h >= 0) && (h < H_);
            cp_async16z(base + (uint32_t)((q_of * 5 + r) * FB_ROW + 8 + lane * 4) * 4,
                        src + h * W_ + lane * 4, hv);
        }
        if (tid < 64)
            asm volatile("cp.async.ca.shared.global [%0], [%1], 16;\n"
                         :: "r"(ow_u32 + (uint32_t)buf * 1024 + (uint32_t)tid * 16),
                            "l"((const char*)g_owp + (size_t)c * 1024 + (size_t)tid * 16));
        cp_async_commit();
    };

    stage(cbase, 0);
    stage(cbase + 1, 1);

    for (int ci = 0; ci < 32; ci++) {
        if (ci == 31) asm volatile("cp.async.wait_group 0;\n");
        else          asm volatile("cp.async.wait_group 1;\n");
        __syncthreads();                       // buffer ci&1 (band + weights) ready

        const float* xb = xs + (ci & 1) * FB_BUF;

        // 4 quadrant reassembly values
        float vq[4];
#pragma unroll
        for (int q = 0; q < 4; q++) {
            const float* qb = xb + q * FB_Q + 6 + tid;   // col = 8 + (tid + dj - 2)
            float s = 0.f;
#pragma unroll
            for (int di = 0; di < 5; di++)
#pragma unroll
                for (int dj = 0; dj < 5; dj++)
                    s += kw[di * 5 + dj] * qb[di * FB_ROW + dj];
            vq[q] = s;
        }

        // cout GEMM update: 32 LDS.128 + 128 FFMA2
        const ulonglong2* wt = (const ulonglong2*)&ows2[ci & 1][0][0];
#pragma unroll
        for (int q = 0; q < 4; q++) {
            unsigned long long v2 = pack2(vq[q], vq[q]);
#pragma unroll
            for (int jj = 0; jj < 16; jj++) {
                ulonglong2 wv = wt[q * 16 + jj];
                fma2(acc2[2*jj],     v2, wv.x);
                fma2(acc2[2*jj + 1], v2, wv.y);
            }
        }

        if (ci < 30) {
            __syncthreads();                   // all reads of buffer ci&1 done
            stage(cbase + ci + 2, ci & 1);
        }
    }

    // store partial: g_pout[half][(n*64+co)*HWD + b*256 + tid]
    float* op = g_pout + (size_t)half * OSTR + (size_t)n * 64 * HWD + (size_t)b * 256 + tid;
#pragma unroll
    for (int j = 0; j < 32; j++) {
        float2 r = unpack2(acc2[j]);
        op[(size_t)j * HWD]        = r.x;
        op[(size_t)(j + 32) * HWD] = r.y;
    }
}

// ---------------------------------------------------------------------------
// Kernel 4: reduce halves + bias -> out. float4, 2048 blocks x 256 threads.
// ---------------------------------------------------------------------------
__global__ void __launch_bounds__(256) k_red(const float* __restrict__ ob,
                                             float* __restrict__ out) {
    const int i4 = blockIdx.x * 256 + threadIdx.x;      // float4 index, 524288 total
    const int co = (i4 >> 12) & 63;                     // (i4*4)/HWD & 63
    float4 a = *((const float4*)g_pout + i4);
    float4 c = *((const float4*)(g_pout + OSTR) + i4);
    float bv = __ldg(ob + co);
    ((float4*)out)[i4] = make_float4(a.x + c.x + bv, a.y + c.y + bv,
                                     a.z + c.z + bv, a.w + c.w + bv);
}

// ---------------------------------------------------------------------------
extern "C" void kernel_launch(void* const* d_in, const int* in_sizes, int n_in,
                              void* d_out, int out_size) {
    const float* x      = (const float*)d_in[0];
    const float* down_w = (const float*)d_in[1];
    const float* down_b = (const float*)d_in[2];
    const float* enc_w  = (const float*)d_in[3];
    const float* enc_b  = (const float*)d_in[4];
    const float* out_w  = (const float*)d_in[5];
    const float* out_b  = (const float*)d_in[6];
    float* out = (float*)d_out;

    static bool attr_set = false;
    if (!attr_set) {
        cudaFuncSetAttribute(k_fuse, cudaFuncAttributeMaxDynamicSharedMemorySize,
                             FB_SMEM);
        attr_set = true;
    }

    k_w2<<<25, 576>>>(enc_w, down_w, down_b);
    k_owp<<<64, 128>>>(out_w);

    dim3 g1(8, 8, 8);                 // z = n*4 + channel-group
    k_enc<<<g1, 128>>>(x);

    k_softmax<<<256, 128>>>(enc_b);

    dim3 gf(64, 2, 2);                // (hd-pair, n, channel-half) = 256 blocks
    k_fuse<<<gf, 256, FB_SMEM>>>(x);

    k_red<<<2048, 256>>>(out_b, out);
}

// round 17
// speedup vs baseline: 1.0367x; 1.0367x over previous
#include <cuda_runtime.h>
#include <cstdint>

#define N_  2
#define C_  64
#define H_  256
#define W_  256
#define HW  (H_*W_)
#define HD  128
#define WD  128
#define HWD (HD*WD)
#define KK  25
#define KP  28                      // padded k-vector stride (112B, float4-aligned)
#define CGS28 (N_*HWD*KP)           // per-channel-group partial stride (padded)

// scratch (device globals per allocation-free rule)
__device__ __align__(16) float2 g_w2d[C_*KK*9];      // folded enc weights, dup'd, [ci][kk][t]
__device__ __align__(16) float g_tb[KK*9];           // per-tap folded bias
__device__ __align__(16) float2 g_owp[C_*4*32];      // out weights packed [c][q][j]={ow[j][4c+q],ow[j+32][4c+q]}
__device__ __align__(16) float g_part[4*CGS28];      // partial logits (padded), 14.7 MB
__device__ __align__(16) float g_k[N_*HWD*KP];       // softmax weights (n,hd,wd,28)

// cp.async helpers
__device__ __forceinline__ void cp_async4(uint32_t dst_smem, const void* src, bool valid) {
    int sz = valid ? 4 : 0;
    asm volatile("cp.async.ca.shared.global [%0], [%1], 4, %2;\n"
                 :: "r"(dst_smem), "l"(src), "r"(sz));
}
__device__ __forceinline__ void cp_async8(uint32_t dst_smem, const void* src) {
    asm volatile("cp.async.ca.shared.global [%0], [%1], 8;\n"
                 :: "r"(dst_smem), "l"(src));
}
__device__ __forceinline__ void cp_async16z(uint32_t dst_smem, const void* src, bool valid) {
    int sz = valid ? 16 : 0;
    asm volatile("cp.async.ca.shared.global [%0], [%1], 16, %2;\n"
                 :: "r"(dst_smem), "l"(src), "r"(sz));
}
__device__ __forceinline__ void cp_async_commit() {
    asm volatile("cp.async.commit_group;\n");
}

// ---- packed fp32x2 helpers (sm_103a FFMA2) ----
__device__ __forceinline__ unsigned long long pack2(float lo, float hi) {
    unsigned long long r;
    asm("mov.b64 %0, {%1, %2};" : "=l"(r) : "f"(lo), "f"(hi));
    return r;
}
__device__ __forceinline__ void fma2(unsigned long long& d,
                                     unsigned long long a, unsigned long long b) {
    asm("fma.rn.f32x2 %0, %1, %2, %0;" : "+l"(d) : "l"(a), "l"(b));
}
__device__ __forceinline__ float2 unpack2(unsigned long long v) {
    float lo, hi;
    asm("mov.b64 {%0, %1}, %2;" : "=f"(lo), "=f"(hi) : "l"(v));
    return make_float2(lo, hi);
}

// ---------------------------------------------------------------------------
// Kernel 0: fold down(1x1) into enc(3x3). Also per-tap bias.
// ---------------------------------------------------------------------------
__global__ void k_w2(const float* __restrict__ ew,
                     const float* __restrict__ dw,
                     const float* __restrict__ db) {
    __shared__ float sew[576];
    __shared__ float sdb[64];
    __shared__ float sdw[64*64];
    const int kk = blockIdx.x;
    const int t  = threadIdx.x;
    sew[t] = ew[kk*576 + t];
    if (t < 64) sdb[t] = db[t];
    for (int i = t; i < 4096; i += 576) sdw[i] = dw[i];
    __syncthreads();

    const int ci = t / 9, rs = t % 9;
    float s = 0.f;
#pragma unroll 8
    for (int c = 0; c < 64; c++) s += sew[c*9 + rs] * sdw[c*64 + ci];
    g_w2d[(ci * KK + kk) * 9 + rs] = make_float2(s, s);

    if (t < 9) {
        float s2 = 0.f;
        for (int c = 0; c < 64; c++) s2 += sew[c*9 + t] * sdb[c];
        g_tb[kk*9 + t] = s2;
    }
}

// ---------------------------------------------------------------------------
// Kernel 0b: pack out-conv weights: g_owp[c][q][j] = {ow[j][4c+q], ow[j+32][4c+q]}
// ---------------------------------------------------------------------------
__global__ void k_owp(const float* __restrict__ ow) {
    const int c = blockIdx.x;        // 0..63
    const int t = threadIdx.x;       // 128: q = t>>5, j = t&31
    const int q = t >> 5, j = t & 31;
    g_owp[c * 128 + q * 32 + j] =
        make_float2(ow[j * 256 + c * 4 + q], ow[(j + 32) * 256 + c * 4 + q]);
}

// ---------------------------------------------------------------------------
// Kernel 1: folded 3x3 stride-2 conv x(64ch) -> 25 partial logits. (unchanged)
// ---------------------------------------------------------------------------
#define ENC_TILE_F (33*36)

__global__ void __launch_bounds__(128) k_enc(const float* __restrict__ x) {
    __shared__ float  tile[2][33][36];
    __shared__ float2 wsd[2][25][9];
    const int n   = blockIdx.z >> 2;
    const int cg  = blockIdx.z & 3;
    const int hd0 = blockIdx.y * 16;
    const int wd0 = blockIdx.x * 16;
    const int tid = threadIdx.x;
    const int tx  = tid & 15;
    const int ty  = tid >> 4;
    const int c0  = cg * 16;

    const int h0 = 2 * hd0 - 1;
    const int w0 = 2 * wd0 - 1;
    const float* src = x + (size_t)n * C_ * HW;
    const uint32_t smem_tile = (uint32_t)__cvta_generic_to_shared(&tile[0][0][0]);
    const uint32_t smem_wsd  = (uint32_t)__cvta_generic_to_shared(&wsd[0][0][0]);

    auto stage = [&](int ci, int buf) {
        const float* sc = src + (size_t)(c0 + ci) * HW;
        const uint32_t tbase = smem_tile + (uint32_t)buf * (ENC_TILE_F * 4);
#pragma unroll
        for (int i = 0; i < 9; i++) {
            int idx = tid + i * 128;
            if (idx < 33*33) {
                int r = idx / 33, cc = idx % 33;
                int h = h0 + r, w = w0 + cc;
                bool ok = (h >= 0 && h < H_ && w >= 0 && w < W_);
                cp_async4(tbase + (uint32_t)(r * 36 + cc) * 4, sc + h * W_ + w, ok);
            }
        }
        const float2* wsrc = g_w2d + (size_t)(c0 + ci) * (KK * 9);
        const uint32_t wbase = smem_wsd + (uint32_t)buf * (KK * 9 * 8);
        cp_async8(wbase + (uint32_t)tid * 8, wsrc + tid);
        if (tid + 128 < 225)
            cp_async8(wbase + (uint32_t)(tid + 128) * 8, wsrc + tid + 128);
        cp_async_commit();
    };

    stage(0, 0);
    stage(1, 1);

    unsigned long long acc2[KK];
#pragma unroll
    for (int kk = 0; kk < KK; kk++) acc2[kk] = 0ULL;

    for (int ci = 0; ci < 16; ci++) {
        if (ci == 15) asm volatile("cp.async.wait_group 0;\n");
        else          asm volatile("cp.async.wait_group 1;\n");
        __syncthreads();

        const float (*tb)[36] = tile[ci & 1];
        unsigned long long v01[9];
#pragma unroll
        for (int r = 0; r < 3; r++)
#pragma unroll
            for (int s = 0; s < 3; s++)
                v01[r*3+s] = pack2(tb[4*ty + r][2*tx + s],
                                   tb[4*ty + 2 + r][2*tx + s]);

        const unsigned long long* wc =
            (const unsigned long long*)&wsd[ci & 1][0][0];
#pragma unroll
        for (int kk = 0; kk < KK; kk++)
#pragma unroll
            for (int t = 0; t < 9; t++)
                fma2(acc2[kk], wc[kk*9 + t], v01[t]);

        if (ci < 14) {
            __syncthreads();
            stage(ci + 2, ci & 1);
        }
    }

    const int wd = wd0 + tx;
    float* dst0 = g_part + cg * CGS28 + ((size_t)((n * HD + hd0 + 2*ty) * WD + wd)) * KP;
    float* dst1 = g_part + cg * CGS28 + ((size_t)((n * HD + hd0 + 2*ty + 1) * WD + wd)) * KP;
#pragma unroll
    for (int kk = 0; kk < KK; kk++) {
        float2 r = unpack2(acc2[kk]);
        dst0[kk] = r.x;
        dst1[kk] = r.y;
    }
}

// ---------------------------------------------------------------------------
// Kernel 2: sum 4 partials + bias + softmax.
// ---------------------------------------------------------------------------
__global__ void __launch_bounds__(128) k_softmax(const float* __restrict__ eb) {
    __shared__ float stb[225];
    __shared__ float seb[25];
    const int tid = threadIdx.x;
    stb[tid] = g_tb[tid];
    if (tid + 128 < 225) stb[tid + 128] = g_tb[tid + 128];
    if (tid < 25)  seb[tid] = eb[tid];
    __syncthreads();

    const int pix = blockIdx.x * 128 + tid;           // 32768 pixels
    const int wd = pix & 127;
    const int hd = (pix >> 7) & 127;

    const float r0 = (hd != 0) ? 1.f : 0.f;
    const float s0 = (wd != 0) ? 1.f : 0.f;
    float m9[9];
    m9[0] = r0 * s0; m9[1] = r0; m9[2] = r0;
    m9[3] = s0;      m9[4] = 1.f; m9[5] = 1.f;
    m9[6] = s0;      m9[7] = 1.f; m9[8] = 1.f;

    const float4* p0 = (const float4*)(g_part + (size_t)pix * KP);
    const float4* p1 = (const float4*)(g_part + CGS28   + (size_t)pix * KP);
    const float4* p2 = (const float4*)(g_part + 2*CGS28 + (size_t)pix * KP);
    const float4* p3 = (const float4*)(g_part + 3*CGS28 + (size_t)pix * KP);
    float a[28];
#pragma unroll
    for (int i = 0; i < 7; i++) {
        float4 v0 = p0[i], v1 = p1[i], v2 = p2[i], v3 = p3[i];
        a[4*i+0] = v0.x + v1.x + v2.x + v3.x;
        a[4*i+1] = v0.y + v1.y + v2.y + v3.y;
        a[4*i+2] = v0.z + v1.z + v2.z + v3.z;
        a[4*i+3] = v0.w + v1.w + v2.w + v3.w;
    }

    float lg[28];
#pragma unroll
    for (int kk = 0; kk < KK; kk++) {
        float v = a[kk] + seb[kk];
#pragma unroll
        for (int t = 0; t < 9; t++) v += m9[t] * stb[kk*9 + t];
        lg[kk] = v;
    }

    float mx = lg[0];
#pragma unroll
    for (int kk = 1; kk < KK; kk++) mx = fmaxf(mx, lg[kk]);
    float sum = 0.f;
#pragma unroll
    for (int kk = 0; kk < KK; kk++) { lg[kk] = expf(lg[kk] - mx); sum += lg[kk]; }
    float inv = 1.f / sum;
#pragma unroll
    for (int kk = 0; kk < KK; kk++) lg[kk] *= inv;
    lg[25] = 0.f; lg[26] = 0.f; lg[27] = 0.f;

    float4* dst = (float4*)(g_k + (size_t)pix * KP);
#pragma unroll
    for (int i = 0; i < 7; i++)
        dst[i] = make_float4(lg[4*i], lg[4*i+1], lg[4*i+2], lg[4*i+3]);
}

// ---------------------------------------------------------------------------
// Kernel 3: FUSED reassembly + 1x1 out-conv, IN-BLOCK quadrant split.
// Grid (64 b, 2 wdh, 2 n) = 256 blocks x 256 threads (~2 blocks/SM, 16 warps
// -> latency hiding that R13's 128-block version lacked). Thread-half
// tq=tid>>7 handles quadrants {2tq, 2tq+1} for the block's 128 pixels
// (hd in {2b,2b+1}, wd in [wdh*64, wdh*64+64)); partial cout accumulators
// merged via the dead band smem at the end. No extra global traffic.
// Band: per quadrant 5 rows x 2 parity segs x 72 floats; every float4 fully
// written each stage (row/col validity -> cp.async zero-fill).
// ---------------------------------------------------------------------------
#define FZ_SEG 72
#define FZ_ROW (2*FZ_SEG)            // 144 floats per (q,r)
#define FZ_QB  (5*FZ_ROW)            // 720 per quadrant
#define FZ_BUF (4*FZ_QB)             // 2880 floats per buffer
#define FZ_SMEM (2*FZ_BUF*4)         // 23,040 B dynamic

__global__ void __launch_bounds__(256, 2) k_fuse(const float* __restrict__ x,
                                                 const float* __restrict__ ob,
                                                 float* __restrict__ out) {
    extern __shared__ float xs[];              // [2][FZ_BUF]; reused for reduction
    __shared__ float2 ows2[2][4][32];          // per-channel out-weight slice
    __shared__ float sob[64];
    const int b   = blockIdx.x;                // hd pair: hd in {2b, 2b+1}
    const int wdh = blockIdx.y;                // wd half
    const int n   = blockIdx.z;
    const int tid = threadIdx.x;               // 256

    const int tq  = tid >> 7;                  // quadrant-half: q in {2tq, 2tq+1}
    const int px  = tid & 127;                 // pixel id within block
    const int hd  = 2 * b + (px >> 6);
    const int wd  = wdh * 64 + (px & 63);
    const int s   = hd & 1;                    // parity seg select

    const uint32_t xs_u32 = (uint32_t)__cvta_generic_to_shared(xs);
    const uint32_t ow_u32 = (uint32_t)__cvta_generic_to_shared(&ows2[0][0][0]);

    if (tid < 64) sob[tid] = ob[tid];

    // softmax weights for this pixel (both halves need them)
    float kw[25];
    {
        const float4* kp = (const float4*)(g_k + (size_t)((n * HD + hd) * WD + wd) * KP);
        float t28[28];
#pragma unroll
        for (int i = 0; i < 7; i++) {
            float4 v = kp[i];
            t28[4*i] = v.x; t28[4*i+1] = v.y; t28[4*i+2] = v.z; t28[4*i+3] = v.w;
        }
#pragma unroll
        for (int kk = 0; kk < KK; kk++) kw[kk] = t28[kk];
    }

    // cout accumulators over this thread's 2 quadrants: acc2[j] = {co=j, co=j+32}
    unsigned long long acc2[32];
#pragma unroll
    for (int j = 0; j < 32; j++) acc2[j] = 0ULL;

    const float* xn = x + (size_t)n * C_ * HW;

    // stage channel c into buffer buf: 720 float4, validity per-float4
    auto stage = [&](int c, int buf) {
        const float* src = xn + (size_t)c * HW;
        const uint32_t base = xs_u32 + (uint32_t)buf * (FZ_BUF * 4);
#pragma unroll
        for (int i = 0; i < 3; i++) {
            int f = tid + i * 256;
            if (f < 720) {
                int qrs = f / 18;              // 0..39
                int c4  = f % 18;              // float4 within seg
                int q   = qrs / 10;
                int rs  = qrs % 10;
                int r   = rs >> 1;
                int sp  = rs & 1;
                int h    = q * 64 + b - 2 + r;
                int xcol = sp * 128 + wdh * 64 - 4 + c4 * 4;
                bool ok = (h >= 0) && (h < H_) && (xcol >= 0) && (xcol <= W_ - 4);
                cp_async16z(base + (uint32_t)(q * FZ_QB + r * FZ_ROW + sp * FZ_SEG + c4 * 4) * 4,
                            src + (size_t)h * W_ + xcol, ok);
            }
        }
        if (tid < 64)
            asm volatile("cp.async.ca.shared.global [%0], [%1], 16;\n"
                         :: "r"(ow_u32 + (uint32_t)buf * 1024 + (uint32_t)tid * 16),
                            "l"((const char*)g_owp + (size_t)c * 1024 + (size_t)tid * 16));
        cp_async_commit();
    };

    stage(0, 0);
    stage(1, 1);

    const int jof = (px & 63) + 2;             // band col for dj=0

    for (int c = 0; c < 64; c++) {
        if (c == 63) asm volatile("cp.async.wait_group 0;\n");
        else         asm volatile("cp.async.wait_group 1;\n");
        __syncthreads();                       // buffer c&1 (band + weights) ready

        const float* xb  = xs + (c & 1) * FZ_BUF;
        const float* qb0 = xb + (2*tq)     * FZ_QB + s * FZ_SEG + jof;
        const float* qb1 = xb + (2*tq + 1) * FZ_QB + s * FZ_SEG + jof;

        // stencil for this half's 2 quadrants: 50 LDS + 50 FFMA
        float v0 = 0.f, v1 = 0.f;
#pragma unroll
        for (int r = 0; r < 5; r++)
#pragma unroll
            for (int dj = 0; dj < 5; dj++) {
                float wv = kw[r * 5 + dj];
                v0 += wv * qb0[r * FZ_ROW + dj];
                v1 += wv * qb1[r * FZ_ROW + dj];
            }

        // cout update: 2 quadrants x 16 ull2 loads + 64 FFMA2
        const ulonglong2* wt = (const ulonglong2*)&ows2[c & 1][0][0];
        unsigned long long va = pack2(v0, v0);
        unsigned long long vb = pack2(v1, v1);
#pragma unroll
        for (int jj = 0; jj < 16; jj++) {
            ulonglong2 wva = wt[(2*tq) * 16 + jj];
            fma2(acc2[2*jj],     va, wva.x);
            fma2(acc2[2*jj + 1], va, wva.y);
        }
#pragma unroll
        for (int jj = 0; jj < 16; jj++) {
            ulonglong2 wvb = wt[(2*tq + 1) * 16 + jj];
            fma2(acc2[2*jj],     vb, wvb.x);
            fma2(acc2[2*jj + 1], vb, wvb.y);
        }

        if (c < 62) {
            __syncthreads();                   // all reads of buffer c&1 done
            stage(c + 2, c & 1);
        }
    }

    // merge the two quadrant-halves through (dead) band smem, 2 rounds of 16 ull
    unsigned long long* ex = (unsigned long long*)xs;   // 128px*16 ull = 16KB < 23KB
#pragma unroll
    for (int half = 0; half < 2; half++) {
        __syncthreads();
        if (tq == 1) {
#pragma unroll
            for (int j = 0; j < 16; j++) ex[j * 128 + px] = acc2[half * 16 + j];
        }
        __syncthreads();
        if (tq == 0) {
#pragma unroll
            for (int j = 0; j < 16; j++) {
                float2 a = unpack2(acc2[half * 16 + j]);
                float2 p = unpack2(ex[j * 128 + px]);
                acc2[half * 16 + j] = pack2(a.x + p.x, a.y + p.y);
            }
        }
    }

    if (tq == 0) {
        // out[(n*64+co)*HWD + hd*WD + wd]
        float* op = out + (size_t)n * 64 * HWD + (size_t)hd * WD + wd;
#pragma unroll
        for (int j = 0; j < 32; j++) {
            float2 r = unpack2(acc2[j]);
            op[(size_t)j * HWD]        = r.x + sob[j];
            op[(size_t)(j + 32) * HWD] = r.y + sob[j + 32];
        }
    }
}

// ---------------------------------------------------------------------------
extern "C" void kernel_launch(void* const* d_in, const int* in_sizes, int n_in,
                              void* d_out, int out_size) {
    const float* x      = (const float*)d_in[0];
    const float* down_w = (const float*)d_in[1];
    const float* down_b = (const float*)d_in[2];
    const float* enc_w  = (const float*)d_in[3];
    const float* enc_b  = (const float*)d_in[4];
    const float* out_w  = (const float*)d_in[5];
    const float* out_b  = (const float*)d_in[6];
    float* out = (float*)d_out;

    k_w2<<<25, 576>>>(enc_w, down_w, down_b);
    k_owp<<<64, 128>>>(out_w);

    dim3 g1(8, 8, 8);                 // z = n*4 + channel-group
    k_enc<<<g1, 128>>>(x);

    k_softmax<<<256, 128>>>(enc_b);

    dim3 gf(64, 2, 2);                // (hd-pair, wd-half, n) = 256 blocks
    k_fuse<<<gf, 256, FZ_SMEM>>>(x, out_b, out);
}